// round 11
// baseline (speedup 1.0000x reference)
#include <cuda_runtime.h>
#include <cuda_bf16.h>
#include <cuda_fp16.h>
#include <cstdint>

namespace {
constexpr int TT = 10;
constexpr int NTILES = 1024;      // 65536 / 64 samples per tile
constexpr int GRID = 148;
constexpr int THREADS = 512;      // 16 warps: 2 m-halves x 8 n-octets
// fp16 B-tiles [256 n][64 k], 128B rows, swizzled
constexpr int U1F = 0, FF = 32768, U2F = 65536;
constexpr int W1T = 98304;        // fp16 [256 n][32 k] (k0-15 data), 64B rows
constexpr int HT1 = 114688;       // h1: + buf*16384 (hi), +8192 (lo); fp16 [64s][64u]
constexpr int HT2 = 147456;       // h2 same layout
constexpr int BIAS1 = 180224, BIAS2 = 181248;   // interleaved [u*4 + gate] f32
constexpr int SMEM_BYTES = 182272;
}

__device__ float g_Wf[64 * 256];
__device__ float g_b2p[256];

__device__ __forceinline__ uint32_t s2u(const void* p) {
    uint32_t a;
    asm("{.reg .u64 t; cvta.to.shared.u64 t,%1; cvt.u32.u64 %0,t;}" : "=r"(a) : "l"(p));
    return a;
}
__device__ __forceinline__ void ldsm4(uint32_t a, uint32_t* r) {
    asm volatile("ldmatrix.sync.aligned.m8n8.x4.shared.b16 {%0,%1,%2,%3},[%4];"
        : "=r"(r[0]), "=r"(r[1]), "=r"(r[2]), "=r"(r[3]) : "r"(a));
}
__device__ __forceinline__ void mmah(float* d, const uint32_t* a, uint32_t b0, uint32_t b1) {
    asm volatile("mma.sync.aligned.m16n8k16.row.col.f32.f16.f16.f32 "
        "{%0,%1,%2,%3},{%4,%5,%6,%7},{%8,%9},{%0,%1,%2,%3};"
        : "+f"(d[0]), "+f"(d[1]), "+f"(d[2]), "+f"(d[3])
        : "r"(a[0]), "r"(a[1]), "r"(a[2]), "r"(a[3]), "r"(b0), "r"(b1));
}
__device__ __forceinline__ float tapx(float x) {
    float r;
    asm("tanh.approx.f32 %0,%1;" : "=f"(r) : "f"(x));
    return r;
}
__device__ __forceinline__ float sigm(float x) { return fmaf(tapx(0.5f * x), 0.5f, 0.5f); }
__device__ __forceinline__ uint32_t pkh(float a, float b) {
    __half2 t = __floats2half2_rn(a, b);
    return *reinterpret_cast<uint32_t*>(&t);
}
__device__ __forceinline__ float hfr(float v) { return __half2float(__float2half(v)); }
__device__ __forceinline__ int sw8(int r) { return (r + (r >> 3)) & 7; }

__global__ void prep_kernel(const float* __restrict__ Wd, const float* __restrict__ bd,
                            const float* __restrict__ W2, const float* __restrict__ b2) {
    const int n = threadIdx.x;
    float s2 = b2[n];
    for (int j = 0; j < 30; ++j) s2 += bd[j] * W2[j * 256 + n];
    g_b2p[n] = s2;
    for (int k = 0; k < 64; ++k) {
        float s = 0.f;
        for (int j = 0; j < 30; ++j) s += Wd[k * 30 + j] * W2[j * 256 + n];
        g_Wf[k * 256 + n] = s;
    }
}

__global__ void __launch_bounds__(THREADS, 1)
rnn_mma_kernel(const float* __restrict__ x, const float* __restrict__ W1,
               const float* __restrict__ U1, const float* __restrict__ b1,
               const float* __restrict__ U2, const float* __restrict__ Wf,
               const float* __restrict__ bf, float* __restrict__ out)
{
    extern __shared__ char sm[];
    const uint32_t sb = s2u(sm);
    const int tid = threadIdx.x, wid = tid >> 5, lid = tid & 31;
    const int mt = wid & 1, nq = wid >> 1;     // m-half (32 samples), unit octet (8 units)
    const int grp = lid >> 2, tig = lid & 3;

    // stored col p -> orig gate col: gate=(p>>3)&3, unit=(p>>5)*8+(p&7)
    auto ocol = [](int p) { return (((p >> 3) & 3) << 6) + ((p >> 5) << 3) + (p & 7); };

    // ---- stage weights once (fp16 single) ----
    auto stageH = [&](const float* src, int off) {
        for (int idx = tid; idx < 2048; idx += THREADS) {
            const int p = idx >> 3, kc = idx & 7;
            const float* s0 = src + ocol(p);
            uint32_t v[4];
#pragma unroll
            for (int i = 0; i < 4; ++i)
                v[i] = pkh(s0[(kc * 8 + 2 * i) * 256], s0[(kc * 8 + 2 * i + 1) * 256]);
            *reinterpret_cast<uint4*>(sm + off + p * 128 + ((kc ^ sw8(p)) << 4)) =
                *reinterpret_cast<uint4*>(v);
        }
    };
    stageH(U1, U1F);
    stageH(g_Wf, FF);
    stageH(U2, U2F);
    for (int idx = tid; idx < 512; idx += THREADS) {   // W1 fp16 [256][32k], data in k0-15
        const int p = idx >> 1, c = idx & 1, oc = ocol(p);
        uint32_t v[4];
#pragma unroll
        for (int i = 0; i < 4; ++i)
            v[i] = pkh(W1[(c * 8 + 2 * i) * 256 + oc], W1[(c * 8 + 2 * i + 1) * 256 + oc]);
        *reinterpret_cast<uint4*>(sm + W1T + p * 64 + ((c ^ (p & 3)) << 4)) =
            *reinterpret_cast<uint4*>(v);
    }
    if (tid < 256) {   // biases interleaved: bi[u*4+g] = b[g*64+u]
        float* b1i = reinterpret_cast<float*>(sm + BIAS1);
        float* b2i = reinterpret_cast<float*>(sm + BIAS2);
        const int u = tid >> 2, g = tid & 3;
        b1i[tid] = b1[g * 64 + u];
        b2i[tid] = g_b2p[g * 64 + u];
    }
    __syncthreads();

    // bias regs: bv[e][gate] for this thread's units u = nq*8 + tig*2 + e
    float b1v[2][4], b2v[2][4];
#pragma unroll
    for (int e = 0; e < 2; ++e) {
        const int u = nq * 8 + tig * 2 + e;
        *reinterpret_cast<float4*>(b1v[e]) =
            *reinterpret_cast<const float4*>(reinterpret_cast<float*>(sm + BIAS1) + u * 4);
        *reinterpret_cast<float4*>(b2v[e]) =
            *reinterpret_cast<const float4*>(reinterpret_cast<float*>(sm + BIAS2) + u * 4);
    }

    auto bAddr = [&](int base, int pair, int kc) -> uint32_t {
        const int n = nq * 32 + pair * 16 + (lid & 15);
        const int c = kc * 2 + (lid >> 4);
        return sb + base + n * 128 + ((c ^ sw8(n)) << 4);
    };
    auto aAddr = [&](int base, int mf, int kc) -> uint32_t {
        const int r = mt * 32 + mf * 16 + (lid & 15);
        const int c = kc * 2 + (lid >> 4);
        return sb + base + r * 128 + ((c ^ sw8(r)) << 4);
    };
    auto wAddr = [&](int pair) -> uint32_t {
        const int n = nq * 32 + pair * 16 + (lid & 15);
        const int c = lid >> 4;
        return sb + W1T + n * 64 + ((c ^ (n & 3)) << 4);
    };
    // fp16 2-term chunk: acc += Ahi*B + Alo*B  (warp tile m32 n32)
    auto rec2 = [&](float (*acc)[4][4], int aBase, int bBase, int kc) {
        uint32_t ah[2][4], al[2][4], bh[8];
        ldsm4(aAddr(aBase, 0, kc), ah[0]); ldsm4(aAddr(aBase, 1, kc), ah[1]);
        ldsm4(aAddr(aBase + 8192, 0, kc), al[0]); ldsm4(aAddr(aBase + 8192, 1, kc), al[1]);
        ldsm4(bAddr(bBase, 0, kc), bh); ldsm4(bAddr(bBase, 1, kc), bh + 4);
#pragma unroll
        for (int m = 0; m < 2; ++m)
#pragma unroll
            for (int jj = 0; jj < 4; ++jj) {
                const int bi = 4 * (jj >> 1) + (jj & 1);
                mmah(acc[m][jj], ah[m], bh[bi], bh[bi + 2]);
                mmah(acc[m][jj], al[m], bh[bi], bh[bi + 2]);
            }
    };
    // acc[m][gate][r] init from bias regs (r&1 = e)
    auto initAcc = [&](float (*acc)[4][4], const float (*bv)[4]) {
#pragma unroll
        for (int m = 0; m < 2; ++m)
#pragma unroll
            for (int j = 0; j < 4; ++j)
#pragma unroll
                for (int r = 0; r < 4; ++r)
                    acc[m][j][r] = bv[r & 1][j];
    };
    // epilogue: jj == gate. 8 cells/thread -> packed fp16 hi/lo h stores
    auto epi = [&](float (*acc)[4][4], float (*cst)[4], int hBase,
                   bool relu, bool head, float (*pout)[2][4]) {
#pragma unroll
        for (int m = 0; m < 2; ++m)
#pragma unroll
            for (int p = 0; p < 2; ++p) {
                float hv[2];
#pragma unroll
                for (int e = 0; e < 2; ++e) {
                    const int r = 2 * p + e;
                    const float iv = sigm(acc[m][0][r]);
                    const float fv = sigm(acc[m][1][r]);
                    const float gv = relu ? fmaxf(acc[m][2][r], 0.f) : tapx(acc[m][2][r]);
                    const float ov = sigm(acc[m][3][r]);
                    const int ci = p * 2 + e;
                    const float cc = fmaf(fv, cst[m][ci], iv * gv);
                    cst[m][ci] = cc;
                    hv[e] = ov * (relu ? fmaxf(cc, 0.f) : tapx(cc));
                    if (head) {
                        const int u = nq * 8 + tig * 2 + e;
                        const float4 w = *reinterpret_cast<const float4*>(Wf + u * 4);
                        float* po = pout[m][p];
                        po[0] = fmaf(hv[e], w.x, po[0]);
                        po[1] = fmaf(hv[e], w.y, po[1]);
                        po[2] = fmaf(hv[e], w.z, po[2]);
                        po[3] = fmaf(hv[e], w.w, po[3]);
                    }
                }
                const int u0 = nq * 8 + tig * 2;
                const int s = mt * 32 + m * 16 + grp + p * 8;
                const int ad = s * 128 + (((u0 >> 3) ^ sw8(s)) << 4) + (u0 & 7) * 2;
                const uint32_t hi2 = pkh(hv[0], hv[1]);
                *reinterpret_cast<uint32_t*>(sm + hBase + ad) = hi2;
                const __half2 hh = *reinterpret_cast<const __half2*>(&hi2);
                const float2 hf = __half22float2(hh);
                *reinterpret_cast<uint32_t*>(sm + hBase + 8192 + ad) =
                    pkh(hv[0] - hf.x, hv[1] - hf.y);
            }
    };

    // ---- persistent tile loop: 64 samples/tile ----
    for (int tile = blockIdx.x; tile < NTILES; tile += gridDim.x) {
        float c1[2][4], c2[2][4], pout[2][2][4];
#pragma unroll
        for (int m = 0; m < 2; ++m)
#pragma unroll
            for (int i = 0; i < 4; ++i) { c1[m][i] = 0.f; c2[m][i] = 0.f; }
#pragma unroll
        for (int m = 0; m < 2; ++m)
#pragma unroll
            for (int h = 0; h < 2; ++h)
#pragma unroll
                for (int i = 0; i < 4; ++i) pout[m][h][i] = 0.f;
        const float* xb = x + (size_t)(tile * 64 + mt * 32 + grp) * (TT * 16) + tig * 2;

        for (int t = 0; t < TT; ++t) {
            const int cb = (t & 1) * 16384, pb = ((t & 1) ^ 1) * 16384;
            float2 v[2][4];
#pragma unroll
            for (int m = 0; m < 2; ++m) {
                const float* px = xb + (size_t)m * 16 * (TT * 16) + t * 16;
                v[m][0] = *reinterpret_cast<const float2*>(px);
                v[m][1] = *reinterpret_cast<const float2*>(px + 8 * TT * 16);
                v[m][2] = *reinterpret_cast<const float2*>(px + 8);
                v[m][3] = *reinterpret_cast<const float2*>(px + 8 * TT * 16 + 8);
            }

            // ---- z1 = b1 + h1@U1 + x@W1 ----
            float acc[2][4][4];
            initAcc(acc, b1v);
            if (t)
#pragma unroll
                for (int kc = 0; kc < 4; ++kc) rec2(acc, HT1 + pb, U1F, kc);
            {
                uint32_t axh[2][4], axl[2][4];
#pragma unroll
                for (int m = 0; m < 2; ++m)
#pragma unroll
                    for (int i = 0; i < 4; ++i) {
                        axh[m][i] = pkh(v[m][i].x, v[m][i].y);
                        axl[m][i] = pkh(v[m][i].x - hfr(v[m][i].x), v[m][i].y - hfr(v[m][i].y));
                    }
                uint32_t bh[8];
                ldsm4(wAddr(0), bh); ldsm4(wAddr(1), bh + 4);
#pragma unroll
                for (int m = 0; m < 2; ++m)
#pragma unroll
                    for (int jj = 0; jj < 4; ++jj) {
                        const int bi = 4 * (jj >> 1) + (jj & 1);
                        mmah(acc[m][jj], axh[m], bh[bi], bh[bi + 2]);
                        mmah(acc[m][jj], axl[m], bh[bi], bh[bi + 2]);
                    }
            }
            epi(acc, c1, HT1 + cb, false, false, nullptr);
            __syncthreads();   // the ONLY barrier per timestep

            // ---- z2 = b2' + h1@Wfused + h2@U2 ----
            float acc2[2][4][4];
            initAcc(acc2, b2v);
#pragma unroll
            for (int kc = 0; kc < 4; ++kc) rec2(acc2, HT1 + cb, FF, kc);
            if (t)
#pragma unroll
                for (int kc = 0; kc < 4; ++kc) rec2(acc2, HT2 + pb, U2F, kc);
            epi(acc2, c2, HT2 + cb, true, t == TT - 1, pout);
            // no barrier needed: bar1(t+1) orders epi2 before any conflicting access
        }

        // ---- head: shfl-reduce over tig (units), smem-reduce over nq ----
#pragma unroll
        for (int m = 0; m < 2; ++m)
#pragma unroll
            for (int h = 0; h < 2; ++h)
#pragma unroll
                for (int o = 0; o < 4; ++o) {
                    pout[m][h][o] += __shfl_xor_sync(0xffffffffu, pout[m][h][o], 1);
                    pout[m][h][o] += __shfl_xor_sync(0xffffffffu, pout[m][h][o], 2);
                }
        float* scr = reinterpret_cast<float*>(sm + HT1);   // h1 buf0 dead (last cb = buf1)
        if (tig == 0)
#pragma unroll
            for (int m = 0; m < 2; ++m)
#pragma unroll
                for (int h = 0; h < 2; ++h) {
                    const int s0 = mt * 32 + m * 16 + grp + h * 8;
                    *reinterpret_cast<float4*>(scr + (s0 * 8 + nq) * 4) =
                        make_float4(pout[m][h][0], pout[m][h][1], pout[m][h][2], pout[m][h][3]);
                }
        __syncthreads();
        if (tid < 256) {
            const int s = tid >> 2, o = tid & 3;
            float vv = bf[o];
#pragma unroll
            for (int q = 0; q < 8; ++q) vv += scr[(s * 8 + q) * 4 + o];
            out[(size_t)tile * 256 + s * 4 + o] = vv;
        }
        __syncthreads();   // scr reads done before next tile's epi1 writes h1
    }
}

extern "C" void kernel_launch(void* const* d_in, const int* in_sizes, int n_in,
                              void* d_out, int out_size) {
    (void)in_sizes; (void)n_in; (void)out_size;
    const float* x  = (const float*)d_in[0];
    const float* W1 = (const float*)d_in[1];
    const float* U1 = (const float*)d_in[2];
    const float* b1 = (const float*)d_in[3];
    const float* Wd = (const float*)d_in[4];
    const float* bd = (const float*)d_in[5];
    const float* W2 = (const float*)d_in[6];
    const float* U2 = (const float*)d_in[7];
    const float* b2 = (const float*)d_in[8];
    const float* Wf = (const float*)d_in[9];
    const float* bf = (const float*)d_in[10];
    float* out = (float*)d_out;

    prep_kernel<<<1, 256>>>(Wd, bd, W2, b2);
    cudaFuncSetAttribute(rnn_mma_kernel, cudaFuncAttributeMaxDynamicSharedMemorySize, SMEM_BYTES);
    rnn_mma_kernel<<<GRID, THREADS, SMEM_BYTES>>>(x, W1, U1, b1, U2, Wf, bf, out);
}

// round 12
// speedup vs baseline: 1.3505x; 1.3505x over previous
#include <cuda_runtime.h>
#include <cuda_bf16.h>
#include <cuda_fp16.h>
#include <cstdint>

namespace {
constexpr int TT = 10;
constexpr int NTILES = 1024;      // 65536 / 64 samples per tile
constexpr int GRID = 148;
// fp16 B-tiles [256 n][64 k], 128B rows, swizzled
constexpr int U1F = 0, FF = 32768, U2F = 65536;
constexpr int W1T = 98304;        // fp16 [256 n][32 k] (k0-15 data), 64B rows
constexpr int HT1 = 114688;       // h1: + buf*16384 (hi), +8192 (lo); fp16 [64s][64u]
constexpr int HT2 = 147456;       // h2: + buf*16384 (hi only; U2 leg single-term)
constexpr int BIAS1 = 180224, BIAS2 = 181248;   // interleaved [u*4 + gate] f32
constexpr int SMEM_BYTES = 182272;
}

__device__ float g_Wf[64 * 256];
__device__ float g_b2p[256];

__device__ __forceinline__ uint32_t s2u(const void* p) {
    uint32_t a;
    asm("{.reg .u64 t; cvta.to.shared.u64 t,%1; cvt.u32.u64 %0,t;}" : "=r"(a) : "l"(p));
    return a;
}
__device__ __forceinline__ void ldsm4(uint32_t a, uint32_t* r) {
    asm volatile("ldmatrix.sync.aligned.m8n8.x4.shared.b16 {%0,%1,%2,%3},[%4];"
        : "=r"(r[0]), "=r"(r[1]), "=r"(r[2]), "=r"(r[3]) : "r"(a));
}
__device__ __forceinline__ void mmah(float* d, const uint32_t* a, uint32_t b0, uint32_t b1) {
    asm volatile("mma.sync.aligned.m16n8k16.row.col.f32.f16.f16.f32 "
        "{%0,%1,%2,%3},{%4,%5,%6,%7},{%8,%9},{%0,%1,%2,%3};"
        : "+f"(d[0]), "+f"(d[1]), "+f"(d[2]), "+f"(d[3])
        : "r"(a[0]), "r"(a[1]), "r"(a[2]), "r"(a[3]), "r"(b0), "r"(b1));
}
__device__ __forceinline__ float tapx(float x) {
    float r;
    asm("tanh.approx.f32 %0,%1;" : "=f"(r) : "f"(x));
    return r;
}
__device__ __forceinline__ float sigm(float x) { return fmaf(tapx(0.5f * x), 0.5f, 0.5f); }
__device__ __forceinline__ uint32_t pkh(float a, float b) {
    __half2 t = __floats2half2_rn(a, b);
    return *reinterpret_cast<uint32_t*>(&t);
}
__device__ __forceinline__ float hfr(float v) { return __half2float(__float2half(v)); }
__device__ __forceinline__ int sw8(int r) { return (r + (r >> 3)) & 7; }

__global__ void prep_kernel(const float* __restrict__ Wd, const float* __restrict__ bd,
                            const float* __restrict__ W2, const float* __restrict__ b2) {
    const int n = threadIdx.x;
    float s2 = b2[n];
    for (int j = 0; j < 30; ++j) s2 += bd[j] * W2[j * 256 + n];
    g_b2p[n] = s2;
    for (int k = 0; k < 64; ++k) {
        float s = 0.f;
        for (int j = 0; j < 30; ++j) s += Wd[k * 30 + j] * W2[j * 256 + n];
        g_Wf[k * 256 + n] = s;
    }
}

__global__ void __launch_bounds__(256, 1)
rnn_mma_kernel(const float* __restrict__ x, const float* __restrict__ W1,
               const float* __restrict__ U1, const float* __restrict__ b1,
               const float* __restrict__ U2, const float* __restrict__ Wf,
               const float* __restrict__ bf, float* __restrict__ out)
{
    extern __shared__ char sm[];
    const uint32_t sb = s2u(sm);
    const int tid = threadIdx.x, wid = tid >> 5, lid = tid & 31;
    const int mt = wid & 1, nq = wid >> 1;
    const int grp = lid >> 2, tig = lid & 3;

    auto ocol = [](int p) { return (((p >> 4) & 3) << 6) + ((p >> 6) << 4) + (p & 15); };

    // ---- stage weights once (fp16 single) ----
    auto stageH = [&](const float* src, int off) {
        for (int idx = tid; idx < 2048; idx += 256) {
            const int p = idx >> 3, kc = idx & 7;
            const float* s0 = src + ocol(p);
            uint32_t v[4];
#pragma unroll
            for (int i = 0; i < 4; ++i)
                v[i] = pkh(s0[(kc * 8 + 2 * i) * 256], s0[(kc * 8 + 2 * i + 1) * 256]);
            *reinterpret_cast<uint4*>(sm + off + p * 128 + ((kc ^ sw8(p)) << 4)) =
                *reinterpret_cast<uint4*>(v);
        }
    };
    stageH(U1, U1F);
    stageH(g_Wf, FF);
    stageH(U2, U2F);
    for (int idx = tid; idx < 512; idx += 256) {    // W1 fp16 [256][32k], data in k0-15
        const int p = idx >> 1, c = idx & 1, oc = ocol(p);
        uint32_t v[4];
#pragma unroll
        for (int i = 0; i < 4; ++i)
            v[i] = pkh(W1[(c * 8 + 2 * i) * 256 + oc], W1[(c * 8 + 2 * i + 1) * 256 + oc]);
        *reinterpret_cast<uint4*>(sm + W1T + p * 64 + ((c ^ (p & 3)) << 4)) =
            *reinterpret_cast<uint4*>(v);
    }
    {   // biases interleaved: bi[u*4+g] = b[g*64+u]
        float* b1i = reinterpret_cast<float*>(sm + BIAS1);
        float* b2i = reinterpret_cast<float*>(sm + BIAS2);
        const int u = tid >> 2, g = tid & 3;
        b1i[tid] = b1[g * 64 + u];
        b2i[tid] = g_b2p[g * 64 + u];
    }
    __syncthreads();

    // bias registers: bv[j2*2+e][gate]
    float b1v[4][4], b2v[4][4];
#pragma unroll
    for (int j2 = 0; j2 < 2; ++j2)
#pragma unroll
        for (int e = 0; e < 2; ++e) {
            const int u = nq * 16 + j2 * 8 + tig * 2 + e;
            *reinterpret_cast<float4*>(b1v[j2 * 2 + e]) =
                *reinterpret_cast<const float4*>(reinterpret_cast<float*>(sm + BIAS1) + u * 4);
            *reinterpret_cast<float4*>(b2v[j2 * 2 + e]) =
                *reinterpret_cast<const float4*>(reinterpret_cast<float*>(sm + BIAS2) + u * 4);
        }

    auto bAddr = [&](int base, int jj, int kc) -> uint32_t {
        const int n = nq * 64 + jj * 16 + (lid & 15);
        const int c = kc * 2 + (lid >> 4);
        return sb + base + n * 128 + ((c ^ sw8(n)) << 4);
    };
    auto aAddr = [&](int base, int mf, int kc) -> uint32_t {
        const int r = mt * 32 + mf * 16 + (lid & 15);
        const int c = kc * 2 + (lid >> 4);
        return sb + base + r * 128 + ((c ^ sw8(r)) << 4);
    };
    auto wAddr = [&](int jj) -> uint32_t {
        const int n = nq * 64 + jj * 16 + (lid & 15);
        const int c = lid >> 4;
        return sb + W1T + n * 64 + ((c ^ (n & 3)) << 4);
    };
    // fp16 2-term chunk: acc += Ahi*B + Alo*B
    auto rec2 = [&](float (*acc)[8][4], int aBase, int bBase, int kc) {
        uint32_t ah[2][4], al[2][4], bh[16];
        ldsm4(aAddr(aBase, 0, kc), ah[0]); ldsm4(aAddr(aBase, 1, kc), ah[1]);
        ldsm4(aAddr(aBase + 8192, 0, kc), al[0]); ldsm4(aAddr(aBase + 8192, 1, kc), al[1]);
#pragma unroll
        for (int jj = 0; jj < 4; ++jj) ldsm4(bAddr(bBase, jj, kc), bh + 4 * jj);
#pragma unroll
        for (int m = 0; m < 2; ++m)
#pragma unroll
            for (int jj = 0; jj < 4; ++jj) {
                mmah(acc[m][2 * jj], ah[m], bh[4 * jj], bh[4 * jj + 2]);
                mmah(acc[m][2 * jj + 1], ah[m], bh[4 * jj + 1], bh[4 * jj + 3]);
                mmah(acc[m][2 * jj], al[m], bh[4 * jj], bh[4 * jj + 2]);
                mmah(acc[m][2 * jj + 1], al[m], bh[4 * jj + 1], bh[4 * jj + 3]);
            }
    };
    // fp16 single-term chunk: acc += Ahi*B   (U1/U2 legs)
    auto rec1 = [&](float (*acc)[8][4], int aBase, int bBase, int kc) {
        uint32_t ah[2][4], bh[16];
        ldsm4(aAddr(aBase, 0, kc), ah[0]); ldsm4(aAddr(aBase, 1, kc), ah[1]);
#pragma unroll
        for (int jj = 0; jj < 4; ++jj) ldsm4(bAddr(bBase, jj, kc), bh + 4 * jj);
#pragma unroll
        for (int m = 0; m < 2; ++m)
#pragma unroll
            for (int jj = 0; jj < 4; ++jj) {
                mmah(acc[m][2 * jj], ah[m], bh[4 * jj], bh[4 * jj + 2]);
                mmah(acc[m][2 * jj + 1], ah[m], bh[4 * jj + 1], bh[4 * jj + 3]);
            }
    };
    auto initAcc = [&](float (*acc)[8][4], const float (*bv)[4]) {
#pragma unroll
        for (int m = 0; m < 2; ++m)
#pragma unroll
            for (int j = 0; j < 8; ++j)
#pragma unroll
                for (int r = 0; r < 4; ++r)
                    acc[m][j][r] = bv[(j & 1) * 2 + (r & 1)][j >> 1];
    };
    // epilogue: LSTM gates (bias pre-added) -> packed fp16 stores (lo optional)
    auto epi = [&](float (*acc)[8][4], float (*cst)[8], int hBase, bool storeLo,
                   bool relu, bool head, float (*pout)[2][4]) {
#pragma unroll
        for (int m = 0; m < 2; ++m)
#pragma unroll
            for (int j2 = 0; j2 < 2; ++j2)
#pragma unroll
                for (int p = 0; p < 2; ++p) {
                    float hv[2];
#pragma unroll
                    for (int e = 0; e < 2; ++e) {
                        const int r = 2 * p + e;
                        const float iv = sigm(acc[m][j2][r]);
                        const float fv = sigm(acc[m][2 + j2][r]);
                        const float gv = relu ? fmaxf(acc[m][4 + j2][r], 0.f)
                                              : tapx(acc[m][4 + j2][r]);
                        const float ov = sigm(acc[m][6 + j2][r]);
                        const int ci = j2 * 4 + r;
                        const float cc = fmaf(fv, cst[m][ci], iv * gv);
                        cst[m][ci] = cc;
                        hv[e] = ov * (relu ? fmaxf(cc, 0.f) : tapx(cc));
                        if (head) {
                            const int u = nq * 16 + j2 * 8 + tig * 2 + e;
                            const float4 w = *reinterpret_cast<const float4*>(Wf + u * 4);
                            float* po = pout[m][p];
                            po[0] = fmaf(hv[e], w.x, po[0]);
                            po[1] = fmaf(hv[e], w.y, po[1]);
                            po[2] = fmaf(hv[e], w.z, po[2]);
                            po[3] = fmaf(hv[e], w.w, po[3]);
                        }
                    }
                    const int u0 = nq * 16 + j2 * 8 + tig * 2;
                    const int s = mt * 32 + m * 16 + grp + p * 8;
                    const int ad = s * 128 + (((u0 >> 3) ^ sw8(s)) << 4) + (u0 & 7) * 2;
                    const uint32_t hi2 = pkh(hv[0], hv[1]);
                    *reinterpret_cast<uint32_t*>(sm + hBase + ad) = hi2;
                    if (storeLo) {
                        const __half2 hh = *reinterpret_cast<const __half2*>(&hi2);
                        const float2 hf = __half22float2(hh);
                        *reinterpret_cast<uint32_t*>(sm + hBase + 8192 + ad) =
                            pkh(hv[0] - hf.x, hv[1] - hf.y);
                    }
                }
    };

    // ---- persistent tile loop: 64 samples/tile ----
    for (int tile = blockIdx.x; tile < NTILES; tile += gridDim.x) {
        float c1[2][8], c2[2][8], pout[2][2][4];
#pragma unroll
        for (int m = 0; m < 2; ++m)
#pragma unroll
            for (int i = 0; i < 8; ++i) { c1[m][i] = 0.f; c2[m][i] = 0.f; }
#pragma unroll
        for (int m = 0; m < 2; ++m)
#pragma unroll
            for (int h = 0; h < 2; ++h)
#pragma unroll
                for (int i = 0; i < 4; ++i) pout[m][h][i] = 0.f;
        const float* xb = x + (size_t)(tile * 64 + mt * 32 + grp) * (TT * 16) + tig * 2;

        for (int t = 0; t < TT; ++t) {
            const int cb = (t & 1) * 16384, pb = ((t & 1) ^ 1) * 16384;
            float2 v[2][4];
#pragma unroll
            for (int m = 0; m < 2; ++m) {
                const float* px = xb + (size_t)m * 16 * (TT * 16) + t * 16;
                v[m][0] = *reinterpret_cast<const float2*>(px);
                v[m][1] = *reinterpret_cast<const float2*>(px + 8 * TT * 16);
                v[m][2] = *reinterpret_cast<const float2*>(px + 8);
                v[m][3] = *reinterpret_cast<const float2*>(px + 8 * TT * 16 + 8);
            }

            // ---- z1 = b1 + h1@U1 (1-term) + x@W1 (2-term) ----
            float acc[2][8][4];
            initAcc(acc, b1v);
            if (t)
#pragma unroll
                for (int kc = 0; kc < 4; ++kc) rec1(acc, HT1 + pb, U1F, kc);
            {
                uint32_t axh[2][4], axl[2][4];
#pragma unroll
                for (int m = 0; m < 2; ++m)
#pragma unroll
                    for (int i = 0; i < 4; ++i) {
                        axh[m][i] = pkh(v[m][i].x, v[m][i].y);
                        axl[m][i] = pkh(v[m][i].x - hfr(v[m][i].x), v[m][i].y - hfr(v[m][i].y));
                    }
                uint32_t bh[16];
#pragma unroll
                for (int jj = 0; jj < 4; ++jj) ldsm4(wAddr(jj), bh + 4 * jj);
#pragma unroll
                for (int m = 0; m < 2; ++m)
#pragma unroll
                    for (int jj = 0; jj < 4; ++jj) {
                        mmah(acc[m][2 * jj], axh[m], bh[4 * jj], bh[4 * jj + 2]);
                        mmah(acc[m][2 * jj + 1], axh[m], bh[4 * jj + 1], bh[4 * jj + 3]);
                        mmah(acc[m][2 * jj], axl[m], bh[4 * jj], bh[4 * jj + 2]);
                        mmah(acc[m][2 * jj + 1], axl[m], bh[4 * jj + 1], bh[4 * jj + 3]);
                    }
            }
            epi(acc, c1, HT1 + cb, true, false, false, nullptr);
            __syncthreads();   // the ONLY barrier per timestep

            // ---- z2 = b2' + h1@Wfused (2-term) + h2@U2 (1-term) ----
            float acc2[2][8][4];
            initAcc(acc2, b2v);
#pragma unroll
            for (int kc = 0; kc < 4; ++kc) rec2(acc2, HT1 + cb, FF, kc);
            if (t)
#pragma unroll
                for (int kc = 0; kc < 4; ++kc) rec1(acc2, HT2 + pb, U2F, kc);
            epi(acc2, c2, HT2 + cb, false, true, t == TT - 1, pout);
            // no barrier: bar1(t+1) orders epi2 before any conflicting access
        }

        // ---- head: shfl-reduce over tig, smem-reduce over nq ----
#pragma unroll
        for (int m = 0; m < 2; ++m)
#pragma unroll
            for (int h = 0; h < 2; ++h)
#pragma unroll
                for (int o = 0; o < 4; ++o) {
                    pout[m][h][o] += __shfl_xor_sync(0xffffffffu, pout[m][h][o], 1);
                    pout[m][h][o] += __shfl_xor_sync(0xffffffffu, pout[m][h][o], 2);
                }
        float* scr = reinterpret_cast<float*>(sm + HT1);   // h1 buf0 dead (last cb = buf1)
        if (tig == 0)
#pragma unroll
            for (int m = 0; m < 2; ++m)
#pragma unroll
                for (int h = 0; h < 2; ++h) {
                    const int s0 = mt * 32 + m * 16 + grp + h * 8;
                    *reinterpret_cast<float4*>(scr + (s0 * 4 + nq) * 4) =
                        make_float4(pout[m][h][0], pout[m][h][1], pout[m][h][2], pout[m][h][3]);
                }
        __syncthreads();
        {
            const int s = tid >> 2, o = tid & 3;
            const float vv = scr[(s * 4 + 0) * 4 + o] + scr[(s * 4 + 1) * 4 + o] +
                             scr[(s * 4 + 2) * 4 + o] + scr[(s * 4 + 3) * 4 + o] + bf[o];
            out[(size_t)tile * 256 + s * 4 + o] = vv;
        }
        __syncthreads();   // scr reads done before next tile's epi1 writes h1
    }
}

extern "C" void kernel_launch(void* const* d_in, const int* in_sizes, int n_in,
                              void* d_out, int out_size) {
    (void)in_sizes; (void)n_in; (void)out_size;
    const float* x  = (const float*)d_in[0];
    const float* W1 = (const float*)d_in[1];
    const float* U1 = (const float*)d_in[2];
    const float* b1 = (const float*)d_in[3];
    const float* Wd = (const float*)d_in[4];
    const float* bd = (const float*)d_in[5];
    const float* W2 = (const float*)d_in[6];
    const float* U2 = (const float*)d_in[7];
    const float* b2 = (const float*)d_in[8];
    const float* Wf = (const float*)d_in[9];
    const float* bf = (const float*)d_in[10];
    float* out = (float*)d_out;

    prep_kernel<<<1, 256>>>(Wd, bd, W2, b2);
    cudaFuncSetAttribute(rnn_mma_kernel, cudaFuncAttributeMaxDynamicSharedMemorySize, SMEM_BYTES);
    rnn_mma_kernel<<<GRID, 256, SMEM_BYTES>>>(x, W1, U1, b1, U2, Wf, bf, out);
}

// round 13
// speedup vs baseline: 1.5874x; 1.1754x over previous
#include <cuda_runtime.h>
#include <cuda_bf16.h>
#include <cuda_fp16.h>
#include <cstdint>

namespace {
constexpr int TT = 10;
constexpr int NTILES = 1024;      // 65536 / 64 samples per tile
constexpr int GRID = 148;
// fp16 B-tiles [256 n][64 k], 128B rows, swizzled
constexpr int U1F = 0, FF = 32768, U2F = 65536;
constexpr int W1T = 98304;        // fp16 [256 n][32 k] (k0-15 data), 64B rows
constexpr int HT1 = 114688;       // h1: + buf*16384; fp16 [64s][64u] (hi only)
constexpr int HT2 = 147456;       // h2: + buf*16384 (hi only)
constexpr int BIAS1 = 180224, BIAS2 = 181248;   // interleaved [u*4 + gate] f32
constexpr int SMEM_BYTES = 182272;
}

__device__ float g_Wf[64 * 256];
__device__ float g_b2p[256];

__device__ __forceinline__ uint32_t s2u(const void* p) {
    uint32_t a;
    asm("{.reg .u64 t; cvta.to.shared.u64 t,%1; cvt.u32.u64 %0,t;}" : "=r"(a) : "l"(p));
    return a;
}
__device__ __forceinline__ void ldsm4(uint32_t a, uint32_t* r) {
    asm volatile("ldmatrix.sync.aligned.m8n8.x4.shared.b16 {%0,%1,%2,%3},[%4];"
        : "=r"(r[0]), "=r"(r[1]), "=r"(r[2]), "=r"(r[3]) : "r"(a));
}
__device__ __forceinline__ void mmah(float* d, const uint32_t* a, uint32_t b0, uint32_t b1) {
    asm volatile("mma.sync.aligned.m16n8k16.row.col.f32.f16.f16.f32 "
        "{%0,%1,%2,%3},{%4,%5,%6,%7},{%8,%9},{%0,%1,%2,%3};"
        : "+f"(d[0]), "+f"(d[1]), "+f"(d[2]), "+f"(d[3])
        : "r"(a[0]), "r"(a[1]), "r"(a[2]), "r"(a[3]), "r"(b0), "r"(b1));
}
__device__ __forceinline__ float tapx(float x) {
    float r;
    asm("tanh.approx.f32 %0,%1;" : "=f"(r) : "f"(x));
    return r;
}
__device__ __forceinline__ float sigm(float x) { return fmaf(tapx(0.5f * x), 0.5f, 0.5f); }
__device__ __forceinline__ uint32_t pkh(float a, float b) {
    __half2 t = __floats2half2_rn(a, b);
    return *reinterpret_cast<uint32_t*>(&t);
}
__device__ __forceinline__ int sw8(int r) { return (r + (r >> 3)) & 7; }

__global__ void prep_kernel(const float* __restrict__ Wd, const float* __restrict__ bd,
                            const float* __restrict__ W2, const float* __restrict__ b2) {
    const int n = threadIdx.x;
    float s2 = b2[n];
    for (int j = 0; j < 30; ++j) s2 += bd[j] * W2[j * 256 + n];
    g_b2p[n] = s2;
    for (int k = 0; k < 64; ++k) {
        float s = 0.f;
        for (int j = 0; j < 30; ++j) s += Wd[k * 30 + j] * W2[j * 256 + n];
        g_Wf[k * 256 + n] = s;
    }
}

__global__ void __launch_bounds__(256, 1)
rnn_mma_kernel(const float* __restrict__ x, const float* __restrict__ W1,
               const float* __restrict__ U1, const float* __restrict__ b1,
               const float* __restrict__ U2, const float* __restrict__ Wf,
               const float* __restrict__ bf, float* __restrict__ out)
{
    extern __shared__ char sm[];
    const uint32_t sb = s2u(sm);
    const int tid = threadIdx.x, wid = tid >> 5, lid = tid & 31;
    const int mt = wid & 1, nq = wid >> 1;
    const int grp = lid >> 2, tig = lid & 3;

    auto ocol = [](int p) { return (((p >> 4) & 3) << 6) + ((p >> 6) << 4) + (p & 15); };

    // ---- stage weights once (fp16 single) ----
    auto stageH = [&](const float* src, int off) {
        for (int idx = tid; idx < 2048; idx += 256) {
            const int p = idx >> 3, kc = idx & 7;
            const float* s0 = src + ocol(p);
            uint32_t v[4];
#pragma unroll
            for (int i = 0; i < 4; ++i)
                v[i] = pkh(s0[(kc * 8 + 2 * i) * 256], s0[(kc * 8 + 2 * i + 1) * 256]);
            *reinterpret_cast<uint4*>(sm + off + p * 128 + ((kc ^ sw8(p)) << 4)) =
                *reinterpret_cast<uint4*>(v);
        }
    };
    stageH(U1, U1F);
    stageH(g_Wf, FF);
    stageH(U2, U2F);
    for (int idx = tid; idx < 512; idx += 256) {    // W1 fp16 [256][32k], data in k0-15
        const int p = idx >> 1, c = idx & 1, oc = ocol(p);
        uint32_t v[4];
#pragma unroll
        for (int i = 0; i < 4; ++i)
            v[i] = pkh(W1[(c * 8 + 2 * i) * 256 + oc], W1[(c * 8 + 2 * i + 1) * 256 + oc]);
        *reinterpret_cast<uint4*>(sm + W1T + p * 64 + ((c ^ (p & 3)) << 4)) =
            *reinterpret_cast<uint4*>(v);
    }
    {   // biases interleaved: bi[u*4+g] = b[g*64+u]
        float* b1i = reinterpret_cast<float*>(sm + BIAS1);
        float* b2i = reinterpret_cast<float*>(sm + BIAS2);
        const int u = tid >> 2, g = tid & 3;
        b1i[tid] = b1[g * 64 + u];
        b2i[tid] = g_b2p[g * 64 + u];
    }
    __syncthreads();

    // bias registers: bv[j2*2+e][gate]
    float b1v[4][4], b2v[4][4];
#pragma unroll
    for (int j2 = 0; j2 < 2; ++j2)
#pragma unroll
        for (int e = 0; e < 2; ++e) {
            const int u = nq * 16 + j2 * 8 + tig * 2 + e;
            *reinterpret_cast<float4*>(b1v[j2 * 2 + e]) =
                *reinterpret_cast<const float4*>(reinterpret_cast<float*>(sm + BIAS1) + u * 4);
            *reinterpret_cast<float4*>(b2v[j2 * 2 + e]) =
                *reinterpret_cast<const float4*>(reinterpret_cast<float*>(sm + BIAS2) + u * 4);
        }

    auto bAddr = [&](int base, int jj, int kc) -> uint32_t {
        const int n = nq * 64 + jj * 16 + (lid & 15);
        const int c = kc * 2 + (lid >> 4);
        return sb + base + n * 128 + ((c ^ sw8(n)) << 4);
    };
    auto aAddr = [&](int base, int mf, int kc) -> uint32_t {
        const int r = mt * 32 + mf * 16 + (lid & 15);
        const int c = kc * 2 + (lid >> 4);
        return sb + base + r * 128 + ((c ^ sw8(r)) << 4);
    };
    auto wAddr = [&](int jj) -> uint32_t {
        const int n = nq * 64 + jj * 16 + (lid & 15);
        const int c = lid >> 4;
        return sb + W1T + n * 64 + ((c ^ (n & 3)) << 4);
    };
    // fp16 single-term chunk: acc += A*B
    auto rec1 = [&](float (*acc)[8][4], int aBase, int bBase, int kc) {
        uint32_t ah[2][4], bh[16];
        ldsm4(aAddr(aBase, 0, kc), ah[0]); ldsm4(aAddr(aBase, 1, kc), ah[1]);
#pragma unroll
        for (int jj = 0; jj < 4; ++jj) ldsm4(bAddr(bBase, jj, kc), bh + 4 * jj);
#pragma unroll
        for (int m = 0; m < 2; ++m)
#pragma unroll
            for (int jj = 0; jj < 4; ++jj) {
                mmah(acc[m][2 * jj], ah[m], bh[4 * jj], bh[4 * jj + 2]);
                mmah(acc[m][2 * jj + 1], ah[m], bh[4 * jj + 1], bh[4 * jj + 3]);
            }
    };
    auto initAcc = [&](float (*acc)[8][4], const float (*bv)[4]) {
#pragma unroll
        for (int m = 0; m < 2; ++m)
#pragma unroll
            for (int j = 0; j < 8; ++j)
#pragma unroll
                for (int r = 0; r < 4; ++r)
                    acc[m][j][r] = bv[(j & 1) * 2 + (r & 1)][j >> 1];
    };
    // epilogue: LSTM gates (bias pre-added) -> packed fp16 hi stores only
    auto epi = [&](float (*acc)[8][4], float (*cst)[8], int hBase,
                   bool relu, bool head, float (*pout)[2][4]) {
#pragma unroll
        for (int m = 0; m < 2; ++m)
#pragma unroll
            for (int j2 = 0; j2 < 2; ++j2)
#pragma unroll
                for (int p = 0; p < 2; ++p) {
                    float hv[2];
#pragma unroll
                    for (int e = 0; e < 2; ++e) {
                        const int r = 2 * p + e;
                        const float iv = sigm(acc[m][j2][r]);
                        const float fv = sigm(acc[m][2 + j2][r]);
                        const float gv = relu ? fmaxf(acc[m][4 + j2][r], 0.f)
                                              : tapx(acc[m][4 + j2][r]);
                        const float ov = sigm(acc[m][6 + j2][r]);
                        const int ci = j2 * 4 + r;
                        const float cc = fmaf(fv, cst[m][ci], iv * gv);
                        cst[m][ci] = cc;
                        hv[e] = ov * (relu ? fmaxf(cc, 0.f) : tapx(cc));
                        if (head) {
                            const int u = nq * 16 + j2 * 8 + tig * 2 + e;
                            const float4 w = *reinterpret_cast<const float4*>(Wf + u * 4);
                            float* po = pout[m][p];
                            po[0] = fmaf(hv[e], w.x, po[0]);
                            po[1] = fmaf(hv[e], w.y, po[1]);
                            po[2] = fmaf(hv[e], w.z, po[2]);
                            po[3] = fmaf(hv[e], w.w, po[3]);
                        }
                    }
                    const int u0 = nq * 16 + j2 * 8 + tig * 2;
                    const int s = mt * 32 + m * 16 + grp + p * 8;
                    const int ad = s * 128 + (((u0 >> 3) ^ sw8(s)) << 4) + (u0 & 7) * 2;
                    *reinterpret_cast<uint32_t*>(sm + hBase + ad) = pkh(hv[0], hv[1]);
                }
    };

    // ---- persistent tile loop: 64 samples/tile ----
    for (int tile = blockIdx.x; tile < NTILES; tile += gridDim.x) {
        float c1[2][8], c2[2][8], pout[2][2][4];
#pragma unroll
        for (int m = 0; m < 2; ++m)
#pragma unroll
            for (int i = 0; i < 8; ++i) { c1[m][i] = 0.f; c2[m][i] = 0.f; }
#pragma unroll
        for (int m = 0; m < 2; ++m)
#pragma unroll
            for (int h = 0; h < 2; ++h)
#pragma unroll
                for (int i = 0; i < 4; ++i) pout[m][h][i] = 0.f;
        const float* xb = x + (size_t)(tile * 64 + mt * 32 + grp) * (TT * 16) + tig * 2;

        for (int t = 0; t < TT; ++t) {
            const int cb = (t & 1) * 16384, pb = ((t & 1) ^ 1) * 16384;
            float2 v[2][4];
#pragma unroll
            for (int m = 0; m < 2; ++m) {
                const float* px = xb + (size_t)m * 16 * (TT * 16) + t * 16;
                v[m][0] = *reinterpret_cast<const float2*>(px);
                v[m][1] = *reinterpret_cast<const float2*>(px + 8 * TT * 16);
                v[m][2] = *reinterpret_cast<const float2*>(px + 8);
                v[m][3] = *reinterpret_cast<const float2*>(px + 8 * TT * 16 + 8);
            }

            // ---- z1 = b1 + h1@U1 + x@W1 (all single-term fp16) ----
            float acc[2][8][4];
            initAcc(acc, b1v);
            if (t)
#pragma unroll
                for (int kc = 0; kc < 4; ++kc) rec1(acc, HT1 + pb, U1F, kc);
            {
                uint32_t axh[2][4];
#pragma unroll
                for (int m = 0; m < 2; ++m)
#pragma unroll
                    for (int i = 0; i < 4; ++i)
                        axh[m][i] = pkh(v[m][i].x, v[m][i].y);
                uint32_t bh[16];
#pragma unroll
                for (int jj = 0; jj < 4; ++jj) ldsm4(wAddr(jj), bh + 4 * jj);
#pragma unroll
                for (int m = 0; m < 2; ++m)
#pragma unroll
                    for (int jj = 0; jj < 4; ++jj) {
                        mmah(acc[m][2 * jj], axh[m], bh[4 * jj], bh[4 * jj + 2]);
                        mmah(acc[m][2 * jj + 1], axh[m], bh[4 * jj + 1], bh[4 * jj + 3]);
                    }
            }
            epi(acc, c1, HT1 + cb, false, false, nullptr);
            __syncthreads();   // the ONLY barrier per timestep

            // ---- z2 = b2' + h1@Wfused + h2@U2 (single-term fp16) ----
            float acc2[2][8][4];
            initAcc(acc2, b2v);
#pragma unroll
            for (int kc = 0; kc < 4; ++kc) rec1(acc2, HT1 + cb, FF, kc);
            if (t)
#pragma unroll
                for (int kc = 0; kc < 4; ++kc) rec1(acc2, HT2 + pb, U2F, kc);
            epi(acc2, c2, HT2 + cb, true, t == TT - 1, pout);
            // no barrier: bar1(t+1) orders epi2 before any conflicting access
        }

        // ---- head: shfl-reduce over tig, smem-reduce over nq ----
#pragma unroll
        for (int m = 0; m < 2; ++m)
#pragma unroll
            for (int h = 0; h < 2; ++h)
#pragma unroll
                for (int o = 0; o < 4; ++o) {
                    pout[m][h][o] += __shfl_xor_sync(0xffffffffu, pout[m][h][o], 1);
                    pout[m][h][o] += __shfl_xor_sync(0xffffffffu, pout[m][h][o], 2);
                }
        float* scr = reinterpret_cast<float*>(sm + HT1);   // h1 buf0 dead (last cb = buf1)
        if (tig == 0)
#pragma unroll
            for (int m = 0; m < 2; ++m)
#pragma unroll
                for (int h = 0; h < 2; ++h) {
                    const int s0 = mt * 32 + m * 16 + grp + h * 8;
                    *reinterpret_cast<float4*>(scr + (s0 * 4 + nq) * 4) =
                        make_float4(pout[m][h][0], pout[m][h][1], pout[m][h][2], pout[m][h][3]);
                }
        __syncthreads();
        {
            const int s = tid >> 2, o = tid & 3;
            const float vv = scr[(s * 4 + 0) * 4 + o] + scr[(s * 4 + 1) * 4 + o] +
                             scr[(s * 4 + 2) * 4 + o] + scr[(s * 4 + 3) * 4 + o] + bf[o];
            out[(size_t)tile * 256 + s * 4 + o] = vv;
        }
        __syncthreads();   // scr reads done before next tile's epi1 writes h1
    }
}

extern "C" void kernel_launch(void* const* d_in, const int* in_sizes, int n_in,
                              void* d_out, int out_size) {
    (void)in_sizes; (void)n_in; (void)out_size;
    const float* x  = (const float*)d_in[0];
    const float* W1 = (const float*)d_in[1];
    const float* U1 = (const float*)d_in[2];
    const float* b1 = (const float*)d_in[3];
    const float* Wd = (const float*)d_in[4];
    const float* bd = (const float*)d_in[5];
    const float* W2 = (const float*)d_in[6];
    const float* U2 = (const float*)d_in[7];
    const float* b2 = (const float*)d_in[8];
    const float* Wf = (const float*)d_in[9];
    const float* bf = (const float*)d_in[10];
    float* out = (float*)d_out;

    prep_kernel<<<1, 256>>>(Wd, bd, W2, b2);
    cudaFuncSetAttribute(rnn_mma_kernel, cudaFuncAttributeMaxDynamicSharedMemorySize, SMEM_BYTES);
    rnn_mma_kernel<<<GRID, 256, SMEM_BYTES>>>(x, W1, U1, b1, U2, Wf, bf, out);
}

// round 14
// speedup vs baseline: 1.6676x; 1.0505x over previous
#include <cuda_runtime.h>
#include <cuda_bf16.h>
#include <cuda_fp16.h>
#include <cstdint>

namespace {
constexpr int TT = 10;
constexpr int NTILES = 1024;      // 65536 / 64 samples per tile
constexpr int GRID = 148;
// fp16 B-tiles [256 n][64 k], 128B rows, swizzled
constexpr int U1F = 0, FF = 32768, U2F = 65536;
constexpr int W1T = 98304;        // fp16 [256 n][32 k] (k0-15 data), 64B rows
constexpr int HT1 = 114688;       // h1: + buf*16384; fp16 [64s][64u] (hi only)
constexpr int HT2 = 147456;       // h2: + buf*16384 (hi only)
constexpr int BIAS1 = 180224, BIAS2 = 181248;   // interleaved [u*4 + gate] f32
constexpr int SMEM_BYTES = 182272;
}

__device__ float g_Wf[64 * 256];
__device__ float g_b2p[256];

__device__ __forceinline__ uint32_t s2u(const void* p) {
    uint32_t a;
    asm("{.reg .u64 t; cvta.to.shared.u64 t,%1; cvt.u32.u64 %0,t;}" : "=r"(a) : "l"(p));
    return a;
}
__device__ __forceinline__ void ldsm4(uint32_t a, uint32_t* r) {
    asm volatile("ldmatrix.sync.aligned.m8n8.x4.shared.b16 {%0,%1,%2,%3},[%4];"
        : "=r"(r[0]), "=r"(r[1]), "=r"(r[2]), "=r"(r[3]) : "r"(a));
}
__device__ __forceinline__ void mmah(float* d, const uint32_t* a, uint32_t b0, uint32_t b1) {
    asm volatile("mma.sync.aligned.m16n8k16.row.col.f32.f16.f16.f32 "
        "{%0,%1,%2,%3},{%4,%5,%6,%7},{%8,%9},{%0,%1,%2,%3};"
        : "+f"(d[0]), "+f"(d[1]), "+f"(d[2]), "+f"(d[3])
        : "r"(a[0]), "r"(a[1]), "r"(a[2]), "r"(a[3]), "r"(b0), "r"(b1));
}
__device__ __forceinline__ float tapx(float x) {
    float r;
    asm("tanh.approx.f32 %0,%1;" : "=f"(r) : "f"(x));
    return r;
}
__device__ __forceinline__ float sigm(float x) { return fmaf(tapx(0.5f * x), 0.5f, 0.5f); }
__device__ __forceinline__ uint32_t pkh(float a, float b) {
    __half2 t = __floats2half2_rn(a, b);
    return *reinterpret_cast<uint32_t*>(&t);
}
__device__ __forceinline__ int sw8(int r) { return (r + (r >> 3)) & 7; }
// named barrier over one m-half (4 warps = 128 threads); ids 1 and 2
#define BAR_HALF(mt) asm volatile("bar.sync %0, 128;" :: "r"(1 + (mt)) : "memory")

__global__ void prep_kernel(const float* __restrict__ Wd, const float* __restrict__ bd,
                            const float* __restrict__ W2, const float* __restrict__ b2) {
    const int n = threadIdx.x;
    float s2 = b2[n];
    for (int j = 0; j < 30; ++j) s2 += bd[j] * W2[j * 256 + n];
    g_b2p[n] = s2;
    for (int k = 0; k < 64; ++k) {
        float s = 0.f;
        for (int j = 0; j < 30; ++j) s += Wd[k * 30 + j] * W2[j * 256 + n];
        g_Wf[k * 256 + n] = s;
    }
}

__global__ void __launch_bounds__(256, 1)
rnn_mma_kernel(const float* __restrict__ x, const float* __restrict__ W1,
               const float* __restrict__ U1, const float* __restrict__ b1,
               const float* __restrict__ U2, const float* __restrict__ Wf,
               const float* __restrict__ bf, float* __restrict__ out)
{
    extern __shared__ char sm[];
    const uint32_t sb = s2u(sm);
    const int tid = threadIdx.x, wid = tid >> 5, lid = tid & 31;
    const int mt = wid & 1, nq = wid >> 1;
    const int grp = lid >> 2, tig = lid & 3;

    auto ocol = [](int p) { return (((p >> 4) & 3) << 6) + ((p >> 6) << 4) + (p & 15); };

    // ---- stage weights once (fp16 single) ----
    auto stageH = [&](const float* src, int off) {
        for (int idx = tid; idx < 2048; idx += 256) {
            const int p = idx >> 3, kc = idx & 7;
            const float* s0 = src + ocol(p);
            uint32_t v[4];
#pragma unroll
            for (int i = 0; i < 4; ++i)
                v[i] = pkh(s0[(kc * 8 + 2 * i) * 256], s0[(kc * 8 + 2 * i + 1) * 256]);
            *reinterpret_cast<uint4*>(sm + off + p * 128 + ((kc ^ sw8(p)) << 4)) =
                *reinterpret_cast<uint4*>(v);
        }
    };
    stageH(U1, U1F);
    stageH(g_Wf, FF);
    stageH(U2, U2F);
    for (int idx = tid; idx < 512; idx += 256) {    // W1 fp16 [256][32k], data in k0-15
        const int p = idx >> 1, c = idx & 1, oc = ocol(p);
        uint32_t v[4];
#pragma unroll
        for (int i = 0; i < 4; ++i)
            v[i] = pkh(W1[(c * 8 + 2 * i) * 256 + oc], W1[(c * 8 + 2 * i + 1) * 256 + oc]);
        *reinterpret_cast<uint4*>(sm + W1T + p * 64 + ((c ^ (p & 3)) << 4)) =
            *reinterpret_cast<uint4*>(v);
    }
    {   // biases interleaved: bi[u*4+g] = b[g*64+u]
        float* b1i = reinterpret_cast<float*>(sm + BIAS1);
        float* b2i = reinterpret_cast<float*>(sm + BIAS2);
        const int u = tid >> 2, g = tid & 3;
        b1i[tid] = b1[g * 64 + u];
        b2i[tid] = g_b2p[g * 64 + u];
    }
    __syncthreads();

    // bias registers: bv[j2*2+e][gate]
    float b1v[4][4], b2v[4][4];
#pragma unroll
    for (int j2 = 0; j2 < 2; ++j2)
#pragma unroll
        for (int e = 0; e < 2; ++e) {
            const int u = nq * 16 + j2 * 8 + tig * 2 + e;
            *reinterpret_cast<float4*>(b1v[j2 * 2 + e]) =
                *reinterpret_cast<const float4*>(reinterpret_cast<float*>(sm + BIAS1) + u * 4);
            *reinterpret_cast<float4*>(b2v[j2 * 2 + e]) =
                *reinterpret_cast<const float4*>(reinterpret_cast<float*>(sm + BIAS2) + u * 4);
        }

    auto bAddr = [&](int base, int jj, int kc) -> uint32_t {
        const int n = nq * 64 + jj * 16 + (lid & 15);
        const int c = kc * 2 + (lid >> 4);
        return sb + base + n * 128 + ((c ^ sw8(n)) << 4);
    };
    auto aAddr = [&](int base, int mf, int kc) -> uint32_t {
        const int r = mt * 32 + mf * 16 + (lid & 15);
        const int c = kc * 2 + (lid >> 4);
        return sb + base + r * 128 + ((c ^ sw8(r)) << 4);
    };
    auto wAddr = [&](int jj) -> uint32_t {
        const int n = nq * 64 + jj * 16 + (lid & 15);
        const int c = lid >> 4;
        return sb + W1T + n * 64 + ((c ^ (n & 3)) << 4);
    };
    // fp16 single-term chunk: acc += A*B
    auto rec1 = [&](float (*acc)[8][4], int aBase, int bBase, int kc) {
        uint32_t ah[2][4], bh[16];
        ldsm4(aAddr(aBase, 0, kc), ah[0]); ldsm4(aAddr(aBase, 1, kc), ah[1]);
#pragma unroll
        for (int jj = 0; jj < 4; ++jj) ldsm4(bAddr(bBase, jj, kc), bh + 4 * jj);
#pragma unroll
        for (int m = 0; m < 2; ++m)
#pragma unroll
            for (int jj = 0; jj < 4; ++jj) {
                mmah(acc[m][2 * jj], ah[m], bh[4 * jj], bh[4 * jj + 2]);
                mmah(acc[m][2 * jj + 1], ah[m], bh[4 * jj + 1], bh[4 * jj + 3]);
            }
    };
    auto initAcc = [&](float (*acc)[8][4], const float (*bv)[4]) {
#pragma unroll
        for (int m = 0; m < 2; ++m)
#pragma unroll
            for (int j = 0; j < 8; ++j)
#pragma unroll
                for (int r = 0; r < 4; ++r)
                    acc[m][j][r] = bv[(j & 1) * 2 + (r & 1)][j >> 1];
    };
    // epilogue: LSTM gates (bias pre-added) -> packed fp16 hi stores (optional)
    auto epi = [&](float (*acc)[8][4], float (*cst)[8], int hBase, bool storeH,
                   bool relu, bool head, float (*pout)[2][4]) {
#pragma unroll
        for (int m = 0; m < 2; ++m)
#pragma unroll
            for (int j2 = 0; j2 < 2; ++j2)
#pragma unroll
                for (int p = 0; p < 2; ++p) {
                    float hv[2];
#pragma unroll
                    for (int e = 0; e < 2; ++e) {
                        const int r = 2 * p + e;
                        const float iv = sigm(acc[m][j2][r]);
                        const float fv = sigm(acc[m][2 + j2][r]);
                        const float gv = relu ? fmaxf(acc[m][4 + j2][r], 0.f)
                                              : tapx(acc[m][4 + j2][r]);
                        const float ov = sigm(acc[m][6 + j2][r]);
                        const int ci = j2 * 4 + r;
                        const float cc = fmaf(fv, cst[m][ci], iv * gv);
                        cst[m][ci] = cc;
                        hv[e] = ov * (relu ? fmaxf(cc, 0.f) : tapx(cc));
                        if (head) {
                            const int u = nq * 16 + j2 * 8 + tig * 2 + e;
                            const float4 w = *reinterpret_cast<const float4*>(Wf + u * 4);
                            float* po = pout[m][p];
                            po[0] = fmaf(hv[e], w.x, po[0]);
                            po[1] = fmaf(hv[e], w.y, po[1]);
                            po[2] = fmaf(hv[e], w.z, po[2]);
                            po[3] = fmaf(hv[e], w.w, po[3]);
                        }
                    }
                    if (storeH) {
                        const int u0 = nq * 16 + j2 * 8 + tig * 2;
                        const int s = mt * 32 + m * 16 + grp + p * 8;
                        const int ad = s * 128 + (((u0 >> 3) ^ sw8(s)) << 4) + (u0 & 7) * 2;
                        *reinterpret_cast<uint32_t*>(sm + hBase + ad) = pkh(hv[0], hv[1]);
                    }
                }
    };

    // ---- persistent tile loop: 64 samples/tile; two independent m-halves ----
    for (int tile = blockIdx.x; tile < NTILES; tile += gridDim.x) {
        float c1[2][8], c2[2][8], pout[2][2][4];
#pragma unroll
        for (int m = 0; m < 2; ++m)
#pragma unroll
            for (int i = 0; i < 8; ++i) { c1[m][i] = 0.f; c2[m][i] = 0.f; }
#pragma unroll
        for (int m = 0; m < 2; ++m)
#pragma unroll
            for (int h = 0; h < 2; ++h)
#pragma unroll
                for (int i = 0; i < 4; ++i) pout[m][h][i] = 0.f;
        const float* xb = x + (size_t)(tile * 64 + mt * 32 + grp) * (TT * 16) + tig * 2;

        for (int t = 0; t < TT; ++t) {
            const int cb = (t & 1) * 16384, pb = ((t & 1) ^ 1) * 16384;
            float2 v[2][4];
#pragma unroll
            for (int m = 0; m < 2; ++m) {
                const float* px = xb + (size_t)m * 16 * (TT * 16) + t * 16;
                v[m][0] = *reinterpret_cast<const float2*>(px);
                v[m][1] = *reinterpret_cast<const float2*>(px + 8 * TT * 16);
                v[m][2] = *reinterpret_cast<const float2*>(px + 8);
                v[m][3] = *reinterpret_cast<const float2*>(px + 8 * TT * 16 + 8);
            }

            // ---- z1 = b1 + h1@U1 + x@W1 (single-term fp16) ----
            float acc[2][8][4];
            initAcc(acc, b1v);
            if (t)
#pragma unroll
                for (int kc = 0; kc < 4; ++kc) rec1(acc, HT1 + pb, U1F, kc);
            {
                uint32_t axh[2][4];
#pragma unroll
                for (int m = 0; m < 2; ++m)
#pragma unroll
                    for (int i = 0; i < 4; ++i)
                        axh[m][i] = pkh(v[m][i].x, v[m][i].y);
                uint32_t bh[16];
#pragma unroll
                for (int jj = 0; jj < 4; ++jj) ldsm4(wAddr(jj), bh + 4 * jj);
#pragma unroll
                for (int m = 0; m < 2; ++m)
#pragma unroll
                    for (int jj = 0; jj < 4; ++jj) {
                        mmah(acc[m][2 * jj], axh[m], bh[4 * jj], bh[4 * jj + 2]);
                        mmah(acc[m][2 * jj + 1], axh[m], bh[4 * jj + 1], bh[4 * jj + 3]);
                    }
            }
            epi(acc, c1, HT1 + cb, true, false, false, nullptr);
            BAR_HALF(mt);   // only this m-half's 4 warps sync (h rows are disjoint)

            // ---- z2 = b2' + h1@Wfused + h2@U2 (single-term fp16) ----
            float acc2[2][8][4];
            initAcc(acc2, b2v);
#pragma unroll
            for (int kc = 0; kc < 4; ++kc) rec1(acc2, HT1 + cb, FF, kc);
            if (t)
#pragma unroll
                for (int kc = 0; kc < 4; ++kc) rec1(acc2, HT2 + pb, U2F, kc);
            epi(acc2, c2, HT2 + cb, t < TT - 1, true, t == TT - 1, pout);
            // no barrier: BAR_HALF(t+1) orders epi2 before any conflicting access
        }

        // ---- head: shfl-reduce over tig, smem-reduce over nq ----
#pragma unroll
        for (int m = 0; m < 2; ++m)
#pragma unroll
            for (int h = 0; h < 2; ++h)
#pragma unroll
                for (int o = 0; o < 4; ++o) {
                    pout[m][h][o] += __shfl_xor_sync(0xffffffffu, pout[m][h][o], 1);
                    pout[m][h][o] += __shfl_xor_sync(0xffffffffu, pout[m][h][o], 2);
                }
        __syncthreads();   // full re-converge: scr (below) aliases the OTHER half's h1 rows
        float* scr = reinterpret_cast<float*>(sm + HT1);   // h1 buf0 dead after full bar
        if (tig == 0)
#pragma unroll
            for (int m = 0; m < 2; ++m)
#pragma unroll
                for (int h = 0; h < 2; ++h) {
                    const int s0 = mt * 32 + m * 16 + grp + h * 8;
                    *reinterpret_cast<float4*>(scr + (s0 * 4 + nq) * 4) =
                        make_float4(pout[m][h][0], pout[m][h][1], pout[m][h][2], pout[m][h][3]);
                }
        __syncthreads();
        {
            const int s = tid >> 2, o = tid & 3;
            const float vv = scr[(s * 4 + 0) * 4 + o] + scr[(s * 4 + 1) * 4 + o] +
                             scr[(s * 4 + 2) * 4 + o] + scr[(s * 4 + 3) * 4 + o] + bf[o];
            out[(size_t)tile * 256 + s * 4 + o] = vv;
        }
        __syncthreads();   // scr reads done before next tile's epi1 writes h1
    }
}

extern "C" void kernel_launch(void* const* d_in, const int* in_sizes, int n_in,
                              void* d_out, int out_size) {
    (void)in_sizes; (void)n_in; (void)out_size;
    const float* x  = (const float*)d_in[0];
    const float* W1 = (const float*)d_in[1];
    const float* U1 = (const float*)d_in[2];
    const float* b1 = (const float*)d_in[3];
    const float* Wd = (const float*)d_in[4];
    const float* bd = (const float*)d_in[5];
    const float* W2 = (const float*)d_in[6];
    const float* U2 = (const float*)d_in[7];
    const float* b2 = (const float*)d_in[8];
    const float* Wf = (const float*)d_in[9];
    const float* bf = (const float*)d_in[10];
    float* out = (float*)d_out;

    prep_kernel<<<1, 256>>>(Wd, bd, W2, b2);
    cudaFuncSetAttribute(rnn_mma_kernel, cudaFuncAttributeMaxDynamicSharedMemorySize, SMEM_BYTES);
    rnn_mma_kernel<<<GRID, 256, SMEM_BYTES>>>(x, W1, U1, b1, U2, Wf, bf, out);
}

// round 15
// speedup vs baseline: 1.6914x; 1.0143x over previous
#include <cuda_runtime.h>
#include <cuda_bf16.h>
#include <cuda_fp16.h>
#include <cstdint>

namespace {
constexpr int TT = 10;
constexpr int NTILES = 1024;      // 65536 / 64 samples per tile
constexpr int GRID = 148;
// fp16 B-tiles [256 n][64 k], 128B rows, swizzled
constexpr int U1F = 0, FF = 32768, U2F = 65536;
constexpr int W1T = 98304;        // fp16 [256 n][32 k] (k0-15 data), 64B rows
constexpr int HT1 = 114688;       // h1: + buf*16384; fp16 [64s][64u] (hi only)
constexpr int HT2 = 147456;       // h2: + buf*16384 (hi only)
constexpr int BIAS1 = 180224, BIAS2 = 181248;   // interleaved [u*4 + gate] f32
constexpr int SMEM_BYTES = 182272;
}

__device__ float g_Wf[64 * 256];
__device__ float g_b2p[256];

__device__ __forceinline__ uint32_t s2u(const void* p) {
    uint32_t a;
    asm("{.reg .u64 t; cvta.to.shared.u64 t,%1; cvt.u32.u64 %0,t;}" : "=r"(a) : "l"(p));
    return a;
}
__device__ __forceinline__ void ldsm4(uint32_t a, uint32_t* r) {
    asm volatile("ldmatrix.sync.aligned.m8n8.x4.shared.b16 {%0,%1,%2,%3},[%4];"
        : "=r"(r[0]), "=r"(r[1]), "=r"(r[2]), "=r"(r[3]) : "r"(a));
}
__device__ __forceinline__ void mmah(float* d, const uint32_t* a, uint32_t b0, uint32_t b1) {
    asm volatile("mma.sync.aligned.m16n8k16.row.col.f32.f16.f16.f32 "
        "{%0,%1,%2,%3},{%4,%5,%6,%7},{%8,%9},{%0,%1,%2,%3};"
        : "+f"(d[0]), "+f"(d[1]), "+f"(d[2]), "+f"(d[3])
        : "r"(a[0]), "r"(a[1]), "r"(a[2]), "r"(a[3]), "r"(b0), "r"(b1));
}
__device__ __forceinline__ float tapx(float x) {
    float r;
    asm("tanh.approx.f32 %0,%1;" : "=f"(r) : "f"(x));
    return r;
}
__device__ __forceinline__ float sigm(float x) { return fmaf(tapx(0.5f * x), 0.5f, 0.5f); }
__device__ __forceinline__ uint32_t pkh(float a, float b) {
    __half2 t = __floats2half2_rn(a, b);
    return *reinterpret_cast<uint32_t*>(&t);
}
__device__ __forceinline__ int sw8(int r) { return (r + (r >> 3)) & 7; }
// named barrier over one m-half (4 warps = 128 threads); ids 1 and 2
#define BAR_HALF(mt) asm volatile("bar.sync %0, 128;" :: "r"(1 + (mt)) : "memory")

__global__ void prep_kernel(const float* __restrict__ Wd, const float* __restrict__ bd,
                            const float* __restrict__ W2, const float* __restrict__ b2) {
    const int n = threadIdx.x;
    float s2 = b2[n];
    for (int j = 0; j < 30; ++j) s2 += bd[j] * W2[j * 256 + n];
    g_b2p[n] = s2;
    for (int k = 0; k < 64; ++k) {
        float s = 0.f;
        for (int j = 0; j < 30; ++j) s += Wd[k * 30 + j] * W2[j * 256 + n];
        g_Wf[k * 256 + n] = s;
    }
}

__global__ void __launch_bounds__(256, 1)
rnn_mma_kernel(const float* __restrict__ x, const float* __restrict__ W1,
               const float* __restrict__ U1, const float* __restrict__ b1,
               const float* __restrict__ U2, const float* __restrict__ Wf,
               const float* __restrict__ bf, float* __restrict__ out)
{
    extern __shared__ char sm[];
    const uint32_t sb = s2u(sm);
    const int tid = threadIdx.x, wid = tid >> 5, lid = tid & 31;
    // KEY CHANGE: each SMSP (wid%4) now hosts one warp from EACH m-half, so one
    // half's MUFU epilogue overlaps the other half's HMMA on the same SMSP.
    const int mt = wid >> 2, nq = wid & 3;
    const int grp = lid >> 2, tig = lid & 3;

    auto ocol = [](int p) { return (((p >> 4) & 3) << 6) + ((p >> 6) << 4) + (p & 15); };

    // ---- stage weights once (fp16 single) ----
    auto stageH = [&](const float* src, int off) {
        for (int idx = tid; idx < 2048; idx += 256) {
            const int p = idx >> 3, kc = idx & 7;
            const float* s0 = src + ocol(p);
            uint32_t v[4];
#pragma unroll
            for (int i = 0; i < 4; ++i)
                v[i] = pkh(s0[(kc * 8 + 2 * i) * 256], s0[(kc * 8 + 2 * i + 1) * 256]);
            *reinterpret_cast<uint4*>(sm + off + p * 128 + ((kc ^ sw8(p)) << 4)) =
                *reinterpret_cast<uint4*>(v);
        }
    };
    stageH(U1, U1F);
    stageH(g_Wf, FF);
    stageH(U2, U2F);
    for (int idx = tid; idx < 512; idx += 256) {    // W1 fp16 [256][32k], data in k0-15
        const int p = idx >> 1, c = idx & 1, oc = ocol(p);
        uint32_t v[4];
#pragma unroll
        for (int i = 0; i < 4; ++i)
            v[i] = pkh(W1[(c * 8 + 2 * i) * 256 + oc], W1[(c * 8 + 2 * i + 1) * 256 + oc]);
        *reinterpret_cast<uint4*>(sm + W1T + p * 64 + ((c ^ (p & 3)) << 4)) =
            *reinterpret_cast<uint4*>(v);
    }
    {   // biases interleaved: bi[u*4+g] = b[g*64+u]
        float* b1i = reinterpret_cast<float*>(sm + BIAS1);
        float* b2i = reinterpret_cast<float*>(sm + BIAS2);
        const int u = tid >> 2, g = tid & 3;
        b1i[tid] = b1[g * 64 + u];
        b2i[tid] = g_b2p[g * 64 + u];
    }
    __syncthreads();

    // bias registers: bv[j2*2+e][gate]
    float b1v[4][4], b2v[4][4];
#pragma unroll
    for (int j2 = 0; j2 < 2; ++j2)
#pragma unroll
        for (int e = 0; e < 2; ++e) {
            const int u = nq * 16 + j2 * 8 + tig * 2 + e;
            *reinterpret_cast<float4*>(b1v[j2 * 2 + e]) =
                *reinterpret_cast<const float4*>(reinterpret_cast<float*>(sm + BIAS1) + u * 4);
            *reinterpret_cast<float4*>(b2v[j2 * 2 + e]) =
                *reinterpret_cast<const float4*>(reinterpret_cast<float*>(sm + BIAS2) + u * 4);
        }

    auto bAddr = [&](int base, int jj, int kc) -> uint32_t {
        const int n = nq * 64 + jj * 16 + (lid & 15);
        const int c = kc * 2 + (lid >> 4);
        return sb + base + n * 128 + ((c ^ sw8(n)) << 4);
    };
    auto aAddr = [&](int base, int mf, int kc) -> uint32_t {
        const int r = mt * 32 + mf * 16 + (lid & 15);
        const int c = kc * 2 + (lid >> 4);
        return sb + base + r * 128 + ((c ^ sw8(r)) << 4);
    };
    auto wAddr = [&](int jj) -> uint32_t {
        const int n = nq * 64 + jj * 16 + (lid & 15);
        const int c = lid >> 4;
        return sb + W1T + n * 64 + ((c ^ (n & 3)) << 4);
    };
    // fp16 single-term chunk: acc += A*B
    auto rec1 = [&](float (*acc)[8][4], int aBase, int bBase, int kc) {
        uint32_t ah[2][4], bh[16];
        ldsm4(aAddr(aBase, 0, kc), ah[0]); ldsm4(aAddr(aBase, 1, kc), ah[1]);
#pragma unroll
        for (int jj = 0; jj < 4; ++jj) ldsm4(bAddr(bBase, jj, kc), bh + 4 * jj);
#pragma unroll
        for (int m = 0; m < 2; ++m)
#pragma unroll
            for (int jj = 0; jj < 4; ++jj) {
                mmah(acc[m][2 * jj], ah[m], bh[4 * jj], bh[4 * jj + 2]);
                mmah(acc[m][2 * jj + 1], ah[m], bh[4 * jj + 1], bh[4 * jj + 3]);
            }
    };
    auto initAcc = [&](float (*acc)[8][4], const float (*bv)[4]) {
#pragma unroll
        for (int m = 0; m < 2; ++m)
#pragma unroll
            for (int j = 0; j < 8; ++j)
#pragma unroll
                for (int r = 0; r < 4; ++r)
                    acc[m][j][r] = bv[(j & 1) * 2 + (r & 1)][j >> 1];
    };
    // epilogue: LSTM gates (bias pre-added) -> packed fp16 hi stores (optional)
    auto epi = [&](float (*acc)[8][4], float (*cst)[8], int hBase, bool storeH,
                   bool relu, bool head, float (*pout)[2][4]) {
#pragma unroll
        for (int m = 0; m < 2; ++m)
#pragma unroll
            for (int j2 = 0; j2 < 2; ++j2)
#pragma unroll
                for (int p = 0; p < 2; ++p) {
                    float hv[2];
#pragma unroll
                    for (int e = 0; e < 2; ++e) {
                        const int r = 2 * p + e;
                        const float iv = sigm(acc[m][j2][r]);
                        const float fv = sigm(acc[m][2 + j2][r]);
                        const float gv = relu ? fmaxf(acc[m][4 + j2][r], 0.f)
                                              : tapx(acc[m][4 + j2][r]);
                        const float ov = sigm(acc[m][6 + j2][r]);
                        const int ci = j2 * 4 + r;
                        const float cc = fmaf(fv, cst[m][ci], iv * gv);
                        cst[m][ci] = cc;
                        hv[e] = ov * (relu ? fmaxf(cc, 0.f) : tapx(cc));
                        if (head) {
                            const int u = nq * 16 + j2 * 8 + tig * 2 + e;
                            const float4 w = *reinterpret_cast<const float4*>(Wf + u * 4);
                            float* po = pout[m][p];
                            po[0] = fmaf(hv[e], w.x, po[0]);
                            po[1] = fmaf(hv[e], w.y, po[1]);
                            po[2] = fmaf(hv[e], w.z, po[2]);
                            po[3] = fmaf(hv[e], w.w, po[3]);
                        }
                    }
                    if (storeH) {
                        const int u0 = nq * 16 + j2 * 8 + tig * 2;
                        const int s = mt * 32 + m * 16 + grp + p * 8;
                        const int ad = s * 128 + (((u0 >> 3) ^ sw8(s)) << 4) + (u0 & 7) * 2;
                        *reinterpret_cast<uint32_t*>(sm + hBase + ad) = pkh(hv[0], hv[1]);
                    }
                }
    };

    // ---- persistent tile loop: 64 samples/tile; two independent m-halves ----
    for (int tile = blockIdx.x; tile < NTILES; tile += gridDim.x) {
        float c1[2][8], c2[2][8], pout[2][2][4];
#pragma unroll
        for (int m = 0; m < 2; ++m)
#pragma unroll
            for (int i = 0; i < 8; ++i) { c1[m][i] = 0.f; c2[m][i] = 0.f; }
#pragma unroll
        for (int m = 0; m < 2; ++m)
#pragma unroll
            for (int h = 0; h < 2; ++h)
#pragma unroll
                for (int i = 0; i < 4; ++i) pout[m][h][i] = 0.f;
        const float* xb = x + (size_t)(tile * 64 + mt * 32 + grp) * (TT * 16) + tig * 2;

        for (int t = 0; t < TT; ++t) {
            const int cb = (t & 1) * 16384, pb = ((t & 1) ^ 1) * 16384;
            float2 v[2][4];
#pragma unroll
            for (int m = 0; m < 2; ++m) {
                const float* px = xb + (size_t)m * 16 * (TT * 16) + t * 16;
                v[m][0] = *reinterpret_cast<const float2*>(px);
                v[m][1] = *reinterpret_cast<const float2*>(px + 8 * TT * 16);
                v[m][2] = *reinterpret_cast<const float2*>(px + 8);
                v[m][3] = *reinterpret_cast<const float2*>(px + 8 * TT * 16 + 8);
            }

            // ---- z1 = b1 + h1@U1 + x@W1 (single-term fp16) ----
            float acc[2][8][4];
            initAcc(acc, b1v);
            if (t)
#pragma unroll
                for (int kc = 0; kc < 4; ++kc) rec1(acc, HT1 + pb, U1F, kc);
            {
                uint32_t axh[2][4];
#pragma unroll
                for (int m = 0; m < 2; ++m)
#pragma unroll
                    for (int i = 0; i < 4; ++i)
                        axh[m][i] = pkh(v[m][i].x, v[m][i].y);
                uint32_t bh[16];
#pragma unroll
                for (int jj = 0; jj < 4; ++jj) ldsm4(wAddr(jj), bh + 4 * jj);
#pragma unroll
                for (int m = 0; m < 2; ++m)
#pragma unroll
                    for (int jj = 0; jj < 4; ++jj) {
                        mmah(acc[m][2 * jj], axh[m], bh[4 * jj], bh[4 * jj + 2]);
                        mmah(acc[m][2 * jj + 1], axh[m], bh[4 * jj + 1], bh[4 * jj + 3]);
                    }
            }
            epi(acc, c1, HT1 + cb, true, false, false, nullptr);
            BAR_HALF(mt);   // only this m-half's 4 warps sync (h rows are disjoint)

            // ---- z2 = b2' + h1@Wfused + h2@U2 (single-term fp16) ----
            float acc2[2][8][4];
            initAcc(acc2, b2v);
#pragma unroll
            for (int kc = 0; kc < 4; ++kc) rec1(acc2, HT1 + cb, FF, kc);
            if (t)
#pragma unroll
                for (int kc = 0; kc < 4; ++kc) rec1(acc2, HT2 + pb, U2F, kc);
            epi(acc2, c2, HT2 + cb, t < TT - 1, true, t == TT - 1, pout);
            // no barrier: BAR_HALF(t+1) orders epi2 before any conflicting access
        }

        // ---- head: shfl-reduce over tig, smem-reduce over nq ----
#pragma unroll
        for (int m = 0; m < 2; ++m)
#pragma unroll
            for (int h = 0; h < 2; ++h)
#pragma unroll
                for (int o = 0; o < 4; ++o) {
                    pout[m][h][o] += __shfl_xor_sync(0xffffffffu, pout[m][h][o], 1);
                    pout[m][h][o] += __shfl_xor_sync(0xffffffffu, pout[m][h][o], 2);
                }
        __syncthreads();   // full re-converge: scr (below) aliases the OTHER half's h1 rows
        float* scr = reinterpret_cast<float*>(sm + HT1);   // h1 buf0 dead after full bar
        if (tig == 0)
#pragma unroll
            for (int m = 0; m < 2; ++m)
#pragma unroll
                for (int h = 0; h < 2; ++h) {
                    const int s0 = mt * 32 + m * 16 + grp + h * 8;
                    *reinterpret_cast<float4*>(scr + (s0 * 4 + nq) * 4) =
                        make_float4(pout[m][h][0], pout[m][h][1], pout[m][h][2], pout[m][h][3]);
                }
        __syncthreads();
        {
            const int s = tid >> 2, o = tid & 3;
            const float vv = scr[(s * 4 + 0) * 4 + o] + scr[(s * 4 + 1) * 4 + o] +
                             scr[(s * 4 + 2) * 4 + o] + scr[(s * 4 + 3) * 4 + o] + bf[o];
            out[(size_t)tile * 256 + s * 4 + o] = vv;
        }
        __syncthreads();   // scr reads done before next tile's epi1 writes h1
    }
}

extern "C" void kernel_launch(void* const* d_in, const int* in_sizes, int n_in,
                              void* d_out, int out_size) {
    (void)in_sizes; (void)n_in; (void)out_size;
    const float* x  = (const float*)d_in[0];
    const float* W1 = (const float*)d_in[1];
    const float* U1 = (const float*)d_in[2];
    const float* b1 = (const float*)d_in[3];
    const float* Wd = (const float*)d_in[4];
    const float* bd = (const float*)d_in[5];
    const float* W2 = (const float*)d_in[6];
    const float* U2 = (const float*)d_in[7];
    const float* b2 = (const float*)d_in[8];
    const float* Wf = (const float*)d_in[9];
    const float* bf = (const float*)d_in[10];
    float* out = (float*)d_out;

    prep_kernel<<<1, 256>>>(Wd, bd, W2, b2);
    cudaFuncSetAttribute(rnn_mma_kernel, cudaFuncAttributeMaxDynamicSharedMemorySize, SMEM_BYTES);
    rnn_mma_kernel<<<GRID, 256, SMEM_BYTES>>>(x, W1, U1, b1, U2, Wf, bf, out);
}